// round 15
// baseline (speedup 1.0000x reference)
#include <cuda_runtime.h>
#include <cuda_bf16.h>
#include <math.h>
#include <stdint.h>

// ---------------- problem constants ----------------
#define S_LEN   2048
#define H_DIM   1024
#define NHEADS  8
#define KVHEADS 4
#define HEADDIM 128
#define NEXP    8
#define FF_DIM  2048
#define QKV_N   2048          // 1024 Q + 512 K + 512 V
#define SCALING_F 0.08838834764831845f
#define SOFTCAP_F 50.0f
#define NEG_F    -1e30f
#define EPS_F    1e-6f
#define JIT2_F   0.02f

// ---------------- scratch (device globals; all f32) ----------------
__device__ float g_x   [S_LEN * H_DIM];
__device__ float g_qkv [S_LEN * QKV_N];
__device__ float g_vt  [KVHEADS * HEADDIM * S_LEN];
__device__ float g_sc  [(size_t)NHEADS * S_LEN * S_LEN];   // exp(scores)
__device__ float g_ls  [NHEADS * S_LEN];                   // row sums of exp (atomic)
__device__ float g_at  [S_LEN * H_DIM];
__device__ float g_ob  [S_LEN * H_DIM];
__device__ float g_h   [S_LEN * H_DIM];
__device__ float g_xm  [S_LEN * H_DIM];
__device__ int   g_tok [NEXP * S_LEN];
__device__ float g_wt  [NEXP * S_LEN];
__device__ int   g_cnt [NEXP];
__device__ float g_a1  [(size_t)NEXP * S_LEN * FF_DIM];    // gelu(xw1)*(xw3)
__device__ float g_moe [S_LEN * H_DIM];

// ---------------- fast math helpers ----------------
__device__ __forceinline__ float fast_tanh(float x) {
    float xc = fminf(fmaxf(x, -15.f), 15.f);
    float t = __expf(2.f * xc);
    return (t - 1.f) / (t + 1.f);
}

// ---------------- small kernels ----------------
// zero ALL atomic-accumulated buffers (moe, at, ob, ls) + counts — graph-replay safe
__global__ void zero_all_kernel(float* __restrict__ moe, float* __restrict__ at,
                                float* __restrict__ ob, float* __restrict__ ls,
                                int* __restrict__ cnt) {
    int i = blockIdx.x * blockDim.x + threadIdx.x;
    if (i < S_LEN * H_DIM) { moe[i] = 0.f; at[i] = 0.f; ob[i] = 0.f; }
    if (i < NHEADS * S_LEN) ls[i] = 0.f;
    if (i < NEXP) cnt[i] = 0;
}

__global__ void rms_kernel(const float* __restrict__ in, const float* __restrict__ w,
                           const float* __restrict__ resid, float* __restrict__ out) {
    int row = blockIdx.x;
    const float* x = in + (size_t)row * H_DIM;
    __shared__ float red[256];
    float ss = 0.f;
    for (int i = threadIdx.x; i < H_DIM; i += 256) { float v = x[i]; ss += v * v; }
    red[threadIdx.x] = ss; __syncthreads();
    for (int s = 128; s > 0; s >>= 1) {
        if (threadIdx.x < s) red[threadIdx.x] += red[threadIdx.x + s];
        __syncthreads();
    }
    float inv = rsqrtf(red[0] * (1.f / H_DIM) + EPS_F);
    for (int i = threadIdx.x; i < H_DIM; i += 256) {
        float y = x[i] * inv * (1.f + w[i]);
        float r = resid ? resid[(size_t)row * H_DIM + i] : 0.f;
        out[(size_t)row * H_DIM + i] = r + y;
    }
}

// fused RoPE over Q (heads 0-7, cols h*128) and K (heads 8-11, cols 1024+(h-8)*128)
__global__ void rope_all_kernel(float* __restrict__ qkv, const float* __restrict__ cs,
                                const float* __restrict__ sn) {
    int idx = blockIdx.x * blockDim.x + threadIdx.x;
    int total = S_LEN * 12 * 64;
    if (idx >= total) return;
    int d = idx & 63;
    int h = (idx >> 6) % 12;
    int s = idx / (64 * 12);
    int col = (h < 8) ? h * HEADDIM : 1024 + (h - 8) * HEADDIM;
    float* row = qkv + (size_t)s * QKV_N + col;
    float x1 = row[d], x2 = row[d + 64];
    float c1 = cs[s * HEADDIM + d],      s1 = sn[s * HEADDIM + d];
    float c2 = cs[s * HEADDIM + d + 64], s2 = sn[s * HEADDIM + d + 64];
    row[d]      = x1 * c1 - x2 * s1;
    row[d + 64] = x2 * c2 + x1 * s2;
}

__global__ void transpose_v_kernel(const float* __restrict__ v, int ld,
                                   float* __restrict__ o) {
    __shared__ float t[32][33];
    int bs = blockIdx.x * 32, bd = blockIdx.y * 32;
    int tx = threadIdx.x, ty = threadIdx.y;
    #pragma unroll
    for (int j = 0; j < 32; j += 8)
        t[ty + j][tx] = v[(size_t)(bs + ty + j) * ld + bd + tx];
    __syncthreads();
    #pragma unroll
    for (int j = 0; j < 32; j += 8)
        o[(size_t)(bd + ty + j) * S_LEN + bs + tx] = t[tx][ty + j];
}

// fused router (8 warps, one logit each) + sparsemixer routing, one block per token
__global__ void route_fused_kernel(const float* __restrict__ xm, const float* __restrict__ wr,
                                   int* __restrict__ tok, float* __restrict__ wt,
                                   int* __restrict__ cnt) {
    int t = blockIdx.x;
    int e = threadIdx.x >> 5, lane = threadIdx.x & 31;
    __shared__ float lg[NEXP];
    const float* x = xm + (size_t)t * H_DIM;
    const float* w = wr + (size_t)e * H_DIM;
    float s = 0.f;
    for (int i = lane * 4; i < H_DIM; i += 128) {
        float4 xv = *(const float4*)(x + i);
        float4 wv = *(const float4*)(w + i);
        s += xv.x * wv.x + xv.y * wv.y + xv.z * wv.z + xv.w * wv.w;
    }
    #pragma unroll
    for (int o = 16; o; o >>= 1) s += __shfl_xor_sync(0xffffffffu, s, o);
    if (lane == 0) lg[e] = s;
    __syncthreads();
    if (threadIdx.x != 0) return;

    float sc[NEXP];
    #pragma unroll
    for (int i = 0; i < NEXP; i++) sc[i] = lg[i];
    float m1 = sc[0]; int sel1 = 0;
    #pragma unroll
    for (int i = 1; i < NEXP; i++) if (sc[i] > m1) { m1 = sc[i]; sel1 = i; }
    float v1[NEXP];
    #pragma unroll
    for (int i = 0; i < NEXP; i++) {
        float den = fmaxf(fabsf(sc[i]), m1);
        v1[i] = (((m1 - sc[i]) / den) > JIT2_F) ? NEG_F : sc[i];
    }
    float mx1 = v1[0];
    #pragma unroll
    for (int i = 1; i < NEXP; i++) mx1 = fmaxf(mx1, v1[i]);
    float sum1 = 0.f;
    #pragma unroll
    for (int i = 0; i < NEXP; i++) sum1 += expf(v1[i] - mx1);
    float mult1 = expf(v1[sel1] - mx1) / sum1;

    float ms[NEXP];
    #pragma unroll
    for (int i = 0; i < NEXP; i++) ms[i] = (i == sel1) ? NEG_F : sc[i];
    float m2 = ms[0]; int sel2 = 0;
    #pragma unroll
    for (int i = 1; i < NEXP; i++) if (ms[i] > m2) { m2 = ms[i]; sel2 = i; }
    float v2[NEXP];
    #pragma unroll
    for (int i = 0; i < NEXP; i++) {
        float den = fmaxf(fabsf(sc[i]), m2);
        v2[i] = (((m2 - sc[i]) / den) > JIT2_F) ? NEG_F : ms[i];
    }
    float mx2 = v2[0];
    #pragma unroll
    for (int i = 1; i < NEXP; i++) mx2 = fmaxf(mx2, v2[i]);
    float sum2 = 0.f;
    #pragma unroll
    for (int i = 0; i < NEXP; i++) sum2 += expf(v2[i] - mx2);
    float mult2 = expf(v2[sel2] - mx2) / sum2;

    int p1 = atomicAdd(&cnt[sel1], 1);
    tok[sel1 * S_LEN + p1] = t; wt[sel1 * S_LEN + p1] = mult1;
    int p2 = atomicAdd(&cnt[sel2], 1);
    tok[sel2 * S_LEN + p2] = t; wt[sel2 * S_LEN + p2] = mult2;
}

// ---------------- GEMM helpers ----------------
__device__ __forceinline__ void mma_bf16(float* c, const uint32_t* a, const uint32_t* b) {
    asm volatile(
        "mma.sync.aligned.m16n8k16.row.col.f32.bf16.bf16.f32 "
        "{%0,%1,%2,%3}, {%4,%5,%6,%7}, {%8,%9}, {%0,%1,%2,%3};\n"
        : "+f"(c[0]), "+f"(c[1]), "+f"(c[2]), "+f"(c[3])
        : "r"(a[0]), "r"(a[1]), "r"(a[2]), "r"(a[3]), "r"(b[0]), "r"(b[1]));
}

__device__ __forceinline__ void ldsm4(uint32_t& r0, uint32_t& r1, uint32_t& r2, uint32_t& r3,
                                      uint32_t saddr) {
    asm volatile("ldmatrix.sync.aligned.m8n8.x4.shared.b16 {%0,%1,%2,%3}, [%4];"
                 : "=r"(r0), "=r"(r1), "=r"(r2), "=r"(r3) : "r"(saddr));
}

// truncation split: hi = top 16 bits, lo = rn-bf16(x - hi); packs 2 values
__device__ __forceinline__ void split2t(float a, float b, uint32_t& h, uint32_t& l) {
    uint32_t ia = __float_as_uint(a), ib = __float_as_uint(b);
    h = __byte_perm(ia, ib, 0x7632);
    float la = a - __uint_as_float(ia & 0xFFFF0000u);
    float lb = b - __uint_as_float(ib & 0xFFFF0000u);
    asm("cvt.rn.bf16x2.f32 %0, %1, %2;" : "=r"(l) : "f"(lb), "f"(la));
}

__device__ __forceinline__ void cpasync16(uint32_t dst, const void* src, bool pred) {
    int sz = pred ? 16 : 0;
    asm volatile("cp.async.cg.shared.global [%0], [%1], 16, %2;\n"
                 :: "r"(dst), "l"(src), "r"(sz));
}
#define CP_COMMIT() asm volatile("cp.async.commit_group;\n" ::: "memory")
#define CP_WAIT1()  asm volatile("cp.async.wait_group 1;\n"  ::: "memory")
#define CP_WAITALL() asm volatile("cp.async.wait_all;\n"     ::: "memory")

// dynamic smem layout (bytes):
//   f32 A stages: 0      + s*8192   (3 stages, 24KB)
//   f32 B stages: 24576  + s*8192   (3 stages, 24KB)
//   bf16 bufs (b=0,1) at 49152 + b*24576: Ah +0, Al +6144, Bh +12288, Bl +18432
#define GSMEM 98304

// EPI: 0 plain/atomic/scatter, 1 = exp(softcap)+causal zero + atomic row-sums,
//      2 = gelu(w1)*w3 pair (with SEG==3)
// CAUSAL: 0 none, 1 scores (skip masked blocks), 2 PV (k limited to m0+128)
// SEG: 0 none, 1 = 3-way B select (QKV), 3 = w1/w3 interleaved-16 (fused MoE up)
// RS: scale output by 1/roww[z*S_LEN + m]
template<int EPI, bool GATHER, bool SCATTER, bool ATOMIC, int CAUSAL, int SEG, bool RS>
__global__ void __launch_bounds__(256, 2)
gemm3f_kernel(const float* __restrict__ A, int lda, long long sAz,
              const float* __restrict__ B, const float* __restrict__ B2,
              const float* __restrict__ B3,
              int ldb, long long sBz, int bdiv,
              float* __restrict__ C, float* __restrict__ C2, int ldc, long long sCz,
              int M, int N, int K, int KS, int seg1, int seg2,
              const int* __restrict__ rowidx, const float* __restrict__ roww,
              const int* __restrict__ counts, float* __restrict__ lsout) {
    extern __shared__ char dsm[];
    int zz = blockIdx.z;
    int z  = zz / KS, kc = zz - z * KS;
    int m0 = blockIdx.y * 128;
    int n0 = blockIdx.x * 128;

    if (CAUSAL == 1 && n0 >= m0 + 128) return;

    int Mact = M;
    const int*   ridx = nullptr;
    const float* rw   = nullptr;
    if (counts) {
        Mact = counts[z];
        ridx = rowidx + z * S_LEN;
        rw   = roww ? (roww + z * S_LEN) : nullptr;
        if (m0 >= Mact) return;
    }

    const float* Bsel = B;
    int nbase = 0;
    if constexpr (SEG == 1) {
        if (n0 >= seg2)      { Bsel = B3; nbase = seg2; }
        else if (n0 >= seg1) { Bsel = B2; nbase = seg1; }
    }

    int keff = (CAUSAL == 2) ? min(K, m0 + 128) : K;
    int chunk = K / KS;
    int kstart = kc * chunk;
    int kend   = min(kstart + chunk, keff);
    if (kstart >= kend) return;

    const float* Az = A + (long long)z * sAz;
    const float* Bz = Bsel + (long long)(z / bdiv) * sBz;

    int tid  = threadIdx.x;
    int lane = tid & 31;
    int warp = tid >> 5;
    int wm = warp >> 2, wn = warp & 3;
    int g  = lane >> 2, tg = lane & 3;

    uint32_t sbase = (uint32_t)__cvta_generic_to_shared(dsm);

    // cp.async staging coordinates (2 chunks of 16B per tile per thread)
    const float* srcA[2]; const float* srcB[2];
    uint32_t dstO[2];
    bool pA[2], pB[2];
    #pragma unroll
    for (int j = 0; j < 2; ++j) {
        int id  = tid + 256 * j;
        int row = id >> 2, c4 = (id & 3) * 4;
        int csw = c4 ^ (4 * (row & 3));
        dstO[j] = (uint32_t)((row * 16 + csw) * 4);
        pA[j] = (m0 + row) < Mact;
        long long ar = 0;
        if (pA[j]) ar = GATHER ? (long long)ridx[m0 + row] : (long long)(m0 + row);
        srcA[j] = Az + ar * (long long)lda + c4;
        if constexpr (SEG == 3) {
            int w   = row >> 5, sub = row & 31;
            int col = (n0 >> 1) + w * 16 + (sub & 15);
            const float* basep = (sub & 16) ? B2 : B;
            srcB[j] = basep + (long long)z * sBz + (long long)col * ldb + c4;
            pB[j] = true;
        } else {
            pB[j] = (n0 + row) < N;
            srcB[j] = Bz + (pB[j] ? (long long)(n0 + row - nbase) : 0ll) * (long long)ldb + c4;
        }
    }

    // ldmatrix lane offsets (bytes), SM_STRIDE = 12 u32 rows
    uint32_t a_lane = (uint32_t)(((lane & 15) * 12 + (lane >> 4) * 4) * 4);
    uint32_t b_lane = (uint32_t)((((lane & 7) + ((lane >> 4) & 1) * 8) * 12
                                  + ((lane >> 3) & 1) * 4) * 4);
    uint32_t awoff = (uint32_t)(wm * 64 * 12 * 4) + a_lane;
    uint32_t bwoff = (uint32_t)(wn * 32 * 12 * 4) + b_lane;

    // convert-phase coordinates
    int crow = tid >> 1, ch = tid & 1;
    int cxm  = 4 * (crow & 3);
    int co0  = crow * 16 + ((8 * ch) ^ cxm);
    int co1  = crow * 16 + ((8 * ch + 4) ^ cxm);
    int cdst = crow * 3 + ch;   // uint4 index: (row*12 + h*4) u32 / 4

    float acc[4][4][4];
    #pragma unroll
    for (int i = 0; i < 4; i++)
        #pragma unroll
        for (int j = 0; j < 4; j++)
            #pragma unroll
            for (int r = 0; r < 4; r++) acc[i][j][r] = 0.f;

    int nk = (kend - kstart) >> 4;

    // prologue: prefetch f32 stages 0,1
    #pragma unroll
    for (int pf = 0; pf < 2; ++pf) {
        if (pf < nk) {
            int k0 = kstart + pf * 16;
            uint32_t aoff = sbase + (uint32_t)(pf * 8192);
            uint32_t boff = sbase + 24576u + (uint32_t)(pf * 8192);
            #pragma unroll
            for (int j = 0; j < 2; ++j) {
                cpasync16(aoff + dstO[j], srcA[j] + k0, pA[j]);
                cpasync16(boff + dstO[j], srcB[j] + k0, pB[j]);
            }
        }
        CP_COMMIT();
    }

    for (int it = 0; it < nk; ++it) {
        CP_WAIT1();
        __syncthreads();   // f32 stage it%3 ready; bf16 buf it&1 free

        int pf = it + 2;
        if (pf < nk) {
            int st = pf % 3;
            int k0 = kstart + pf * 16;
            uint32_t aoff = sbase + (uint32_t)(st * 8192);
            uint32_t boff = sbase + 24576u + (uint32_t)(st * 8192);
            #pragma unroll
            for (int j = 0; j < 2; ++j) {
                cpasync16(aoff + dstO[j], srcA[j] + k0, pA[j]);
                cpasync16(boff + dstO[j], srcB[j] + k0, pB[j]);
            }
        }
        CP_COMMIT();

        int cs = it % 3, cb = it & 1;
        // ---- convert f32 stage -> hi/lo bf16 tiles (split once per element)
        {
            const float* fA = (const float*)(dsm + (size_t)cs * 8192);
            const float* fB = (const float*)(dsm + 24576 + (size_t)cs * 8192);
            uint4* Ah = (uint4*)(dsm + 49152 + (size_t)cb * 24576);
            uint4* Al = (uint4*)(dsm + 49152 + (size_t)cb * 24576 + 6144);
            uint4* Bh = (uint4*)(dsm + 49152 + (size_t)cb * 24576 + 12288);
            uint4* Bl = (uint4*)(dsm + 49152 + (size_t)cb * 24576 + 18432);
            float4 a0 = *(const float4*)(fA + co0);
            float4 a1 = *(const float4*)(fA + co1);
            uint4 hh, ll;
            split2t(a0.x, a0.y, hh.x, ll.x); split2t(a0.z, a0.w, hh.y, ll.y);
            split2t(a1.x, a1.y, hh.z, ll.z); split2t(a1.z, a1.w, hh.w, ll.w);
            Ah[cdst] = hh; Al[cdst] = ll;
            float4 b0 = *(const float4*)(fB + co0);
            float4 b1 = *(const float4*)(fB + co1);
            split2t(b0.x, b0.y, hh.x, ll.x); split2t(b0.z, b0.w, hh.y, ll.y);
            split2t(b1.x, b1.y, hh.z, ll.z); split2t(b1.z, b1.w, hh.w, ll.w);
            Bh[cdst] = hh; Bl[cdst] = ll;
        }
        __syncthreads();   // bf16 tiles ready

        // ---- fragment loads (ldmatrix) + pass-ordered MMAs
        uint32_t bb     = sbase + 49152u + (uint32_t)(cb * 24576);
        uint32_t abase  = bb + awoff;
        uint32_t albase = bb + 6144u + awoff;
        uint32_t bbase  = bb + 12288u + bwoff;
        uint32_t blbase = bb + 18432u + bwoff;

        uint32_t bh[4][2], bl[4][2];
        ldsm4(bh[0][0], bh[0][1], bh[1][0], bh[1][1], bbase);
        ldsm4(bh[2][0], bh[2][1], bh[3][0], bh[3][1], bbase + 768);
        ldsm4(bl[0][0], bl[0][1], bl[1][0], bl[1][1], blbase);
        ldsm4(bl[2][0], bl[2][1], bl[3][0], bl[3][1], blbase + 768);

        #pragma unroll
        for (int mt = 0; mt < 4; ++mt) {
            uint32_t ah[4], al[4];
            ldsm4(ah[0], ah[1], ah[2], ah[3], abase + mt * 768);
            ldsm4(al[0], al[1], al[2], al[3], albase + mt * 768);
            #pragma unroll
            for (int nt = 0; nt < 4; ++nt) mma_bf16(acc[mt][nt], ah, bh[nt]);
            #pragma unroll
            for (int nt = 0; nt < 4; ++nt) mma_bf16(acc[mt][nt], ah, bl[nt]);
            #pragma unroll
            for (int nt = 0; nt < 4; ++nt) mma_bf16(acc[mt][nt], al, bh[nt]);
        }
    }
    CP_WAITALL();

    // ---- epilogue
    float* Cz = C + (long long)z * sCz;
    if constexpr (EPI == 2) {
        // fused gelu(xw1)*(xw3) with fast tanh
        #pragma unroll
        for (int mt = 0; mt < 4; ++mt) {
            int row0 = m0 + wm * 64 + mt * 16 + g;
            #pragma unroll
            for (int nt = 0; nt < 2; ++nt) {
                int col0 = (n0 >> 1) + wn * 16 + nt * 8 + 2 * tg;
                #pragma unroll
                for (int r = 0; r < 4; ++r) {
                    int m = row0 + (r >> 1) * 8;
                    if (m >= Mact) continue;
                    int col = col0 + (r & 1);
                    float v1 = acc[mt][nt][r];
                    float v3 = acc[mt][nt + 2][r];
                    float gg = 0.5f * v1 * (1.f + fast_tanh(0.7978845608028654f *
                               (v1 + 0.044715f * v1 * v1 * v1)));
                    Cz[(long long)m * ldc + col] = gg * v3;
                }
            }
        }
        return;
    }
    const float* rsc = nullptr;
    if constexpr (RS) rsc = roww + (long long)z * S_LEN;
    float rs[4][2];
    if constexpr (EPI == 1) {
        #pragma unroll
        for (int i = 0; i < 4; i++) { rs[i][0] = 0.f; rs[i][1] = 0.f; }
    }
    #pragma unroll
    for (int mt = 0; mt < 4; ++mt) {
        int row0 = m0 + wm * 64 + mt * 16 + g;
        #pragma unroll
        for (int nt = 0; nt < 4; ++nt) {
            int col0 = n0 + wn * 32 + nt * 8 + 2 * tg;
            #pragma unroll
            for (int r = 0; r < 4; ++r) {
                int m = row0 + (r >> 1) * 8;
                int n = col0 + (r & 1);
                if (m >= Mact || n >= N) continue;
                float v = acc[mt][nt][r];
                if constexpr (EPI == 1) {
                    float e = 0.f;
                    if (n <= m)
                        e = __expf(SOFTCAP_F * fast_tanh(v * (SCALING_F / SOFTCAP_F)));
                    Cz[(long long)m * ldc + n] = e;
                    rs[mt][r >> 1] += e;
                } else {
                    if constexpr (RS) v = v / rsc[m];
                    if constexpr (SCATTER) {
                        atomicAdd(&Cz[(long long)ridx[m] * ldc + n], rw[m] * v);
                    } else if constexpr (ATOMIC) {
                        atomicAdd(&Cz[(long long)m * ldc + n], v);
                    } else {
                        Cz[(long long)m * ldc + n] = v;
                    }
                }
            }
        }
    }
    if constexpr (EPI == 1) {
        float* lsz = lsout + (long long)z * S_LEN;
        #pragma unroll
        for (int mt = 0; mt < 4; ++mt)
            #pragma unroll
            for (int rh = 0; rh < 2; ++rh) {
                float s = rs[mt][rh];
                s += __shfl_xor_sync(0xffffffffu, s, 1);
                s += __shfl_xor_sync(0xffffffffu, s, 2);
                if (tg == 0) {
                    int m = m0 + wm * 64 + mt * 16 + g + 8 * rh;
                    atomicAdd(&lsz[m], s);
                }
            }
    }
}

// ---------------- launcher ----------------
#define KSPV 8

extern "C" void kernel_launch(void* const* d_in, const int* in_sizes, int n_in,
                              void* d_out, int out_size) {
    const float* hidden = (const float*)d_in[0];
    const float* cosb   = (const float*)d_in[1];
    const float* sinb   = (const float*)d_in[2];
    const float* wq     = (const float*)d_in[4];
    const float* wk     = (const float*)d_in[5];
    const float* wv     = (const float*)d_in[6];
    const float* wo     = (const float*)d_in[7];
    const float* wr     = (const float*)d_in[8];
    const float* w1     = (const float*)d_in[9];
    const float* w2     = (const float*)d_in[10];
    const float* w3     = (const float*)d_in[11];
    const float* ln_in  = (const float*)d_in[12];
    const float* ln_pa  = (const float*)d_in[13];
    const float* ln_pf  = (const float*)d_in[14];
    const float* ln_po  = (const float*)d_in[15];
    float* out = (float*)d_out;

    float *xb,*qkvb,*vtb,*scb,*lsb,*atb,*obb,*hb,*xmb,*wtb,*a1b,*moeb;
    int *tokb,*cntb;
    cudaGetSymbolAddress((void**)&xb, g_x);    cudaGetSymbolAddress((void**)&qkvb,g_qkv);
    cudaGetSymbolAddress((void**)&vtb,g_vt);   cudaGetSymbolAddress((void**)&scb,g_sc);
    cudaGetSymbolAddress((void**)&lsb,g_ls);
    cudaGetSymbolAddress((void**)&atb,g_at);   cudaGetSymbolAddress((void**)&obb,g_ob);
    cudaGetSymbolAddress((void**)&hb, g_h);    cudaGetSymbolAddress((void**)&xmb,g_xm);
    cudaGetSymbolAddress((void**)&wtb,g_wt);
    cudaGetSymbolAddress((void**)&a1b,g_a1);
    cudaGetSymbolAddress((void**)&moeb,g_moe);
    cudaGetSymbolAddress((void**)&tokb,g_tok); cudaGetSymbolAddress((void**)&cntb,g_cnt);

    // dynamic-smem opt-in for every GEMM instantiation (host-side, idempotent)
    cudaFuncSetAttribute(gemm3f_kernel<0,false,false,false,0,1,false>,
                         cudaFuncAttributeMaxDynamicSharedMemorySize, GSMEM);
    cudaFuncSetAttribute(gemm3f_kernel<1,false,false,false,1,0,false>,
                         cudaFuncAttributeMaxDynamicSharedMemorySize, GSMEM);
    cudaFuncSetAttribute(gemm3f_kernel<0,false,false,true,2,0,true>,
                         cudaFuncAttributeMaxDynamicSharedMemorySize, GSMEM);
    cudaFuncSetAttribute(gemm3f_kernel<0,false,false,true,0,0,false>,
                         cudaFuncAttributeMaxDynamicSharedMemorySize, GSMEM);
    cudaFuncSetAttribute(gemm3f_kernel<2,true,false,false,0,3,false>,
                         cudaFuncAttributeMaxDynamicSharedMemorySize, GSMEM);
    cudaFuncSetAttribute(gemm3f_kernel<0,false,true,false,0,0,false>,
                         cudaFuncAttributeMaxDynamicSharedMemorySize, GSMEM);

    zero_all_kernel<<<(S_LEN * H_DIM + 255) / 256, 256>>>(moeb, atb, obb, lsb, cntb);
    rms_kernel<<<S_LEN, 256>>>(hidden, ln_in, nullptr, xb);

    // merged QKV projection: N = 1024(Q) + 512(K) + 512(V)
    gemm3f_kernel<0,false,false,false,0,1,false><<<dim3(16,16,1),256,GSMEM>>>(
        xb, H_DIM, 0, wq, wk, wv, H_DIM, 0, 1,
        qkvb, nullptr, QKV_N, 0,
        S_LEN, QKV_N, H_DIM, 1, 1024, 1536, nullptr, nullptr, nullptr, nullptr);

    // fused RoPE over Q and K heads
    rope_all_kernel<<<(S_LEN*12*64+255)/256, 256>>>(qkvb, cosb, sinb);
    transpose_v_kernel<<<dim3(S_LEN/32, KVHEADS*HEADDIM/32), dim3(32,8)>>>(qkvb + 1536, QKV_N, vtb);

    // attention scores -> exp(softcap) + row sums (fused softmax, fast math)
    gemm3f_kernel<1,false,false,false,1,0,false><<<dim3(16,16,NHEADS),256,GSMEM>>>(
        qkvb, QKV_N, HEADDIM, qkvb + 1024, nullptr, nullptr, QKV_N, HEADDIM, 2,
        scb, nullptr, S_LEN, (long long)S_LEN*S_LEN,
        S_LEN, S_LEN, HEADDIM, 1, 0, 0, nullptr, nullptr, nullptr, lsb);

    // P @ V^T: causal k-limit + split-K=8 atomic; normalize by 1/ls[m]
    gemm3f_kernel<0,false,false,true,2,0,true><<<dim3(1,16,NHEADS*KSPV),256,GSMEM>>>(
        scb, S_LEN, (long long)S_LEN*S_LEN, vtb, nullptr, nullptr, S_LEN,
        (long long)HEADDIM*S_LEN, 2,
        atb, nullptr, H_DIM, HEADDIM,
        S_LEN, HEADDIM, S_LEN, KSPV, 0, 0, nullptr, lsb, nullptr, nullptr);

    // O projection (split-K=2, atomic into zeroed g_ob)
    gemm3f_kernel<0,false,false,true,0,0,false><<<dim3(8,16,2),256,GSMEM>>>(
        atb, H_DIM, 0, wo, nullptr, nullptr, H_DIM, 0, 1,
        obb, nullptr, H_DIM, 0,
        S_LEN, H_DIM, H_DIM, 2, 0, 0, nullptr, nullptr, nullptr, nullptr);

    rms_kernel<<<S_LEN, 256>>>(obb, ln_pa, hidden, hb);
    rms_kernel<<<S_LEN, 256>>>(hb, ln_pf, nullptr, xmb);

    // fused router + sparsemixer routing
    route_fused_kernel<<<S_LEN, 256>>>(xmb, wr, tokb, wtb, cntb);

    // fused MoE up: w1/w3 interleaved-16, gelu(xw1)*(xw3) epilogue -> a1 only
    gemm3f_kernel<2,true,false,false,0,3,false><<<dim3(32,16,NEXP),256,GSMEM>>>(
        xmb, H_DIM, 0, w1, w3, nullptr, H_DIM, (long long)FF_DIM*H_DIM, 1,
        a1b, nullptr, FF_DIM, (long long)S_LEN*FF_DIM,
        S_LEN, 2*FF_DIM, H_DIM, 1, 0, 0, tokb, nullptr, cntb, nullptr);

    // MoE down-projection: split-K=2 + weighted scatter-add
    gemm3f_kernel<0,false,true,false,0,0,false><<<dim3(8,16,NEXP*2),256,GSMEM>>>(
        a1b, FF_DIM, (long long)S_LEN*FF_DIM, w2, nullptr, nullptr, FF_DIM,
        (long long)H_DIM*FF_DIM, 1,
        moeb, nullptr, H_DIM, 0,
        S_LEN, H_DIM, FF_DIM, 2, 0, 0, tokb, wtb, cntb, nullptr);

    rms_kernel<<<S_LEN, 256>>>(moeb, ln_po, hb, out);
}

// round 16
// speedup vs baseline: 1.0298x; 1.0298x over previous
#include <cuda_runtime.h>
#include <cuda_bf16.h>
#include <math.h>
#include <stdint.h>

// ---------------- problem constants ----------------
#define S_LEN   2048
#define H_DIM   1024
#define NHEADS  8
#define KVHEADS 4
#define HEADDIM 128
#define NEXP    8
#define FF_DIM  2048
#define QKV_N   2048          // 1024 Q + 512 K + 512 V
#define SCALING_F 0.08838834764831845f
#define SOFTCAP_F 50.0f
#define NEG_F    -1e30f
#define EPS_F    1e-6f
#define JIT2_F   0.02f

// ---------------- scratch (device globals; all f32) ----------------
__device__ float g_x   [S_LEN * H_DIM];
__device__ float g_qkv [S_LEN * QKV_N];
__device__ float g_vt  [KVHEADS * HEADDIM * S_LEN];
__device__ float g_sc  [(size_t)NHEADS * S_LEN * S_LEN];   // exp(scores)
__device__ float g_ls  [NHEADS * S_LEN];                   // row sums of exp (atomic)
__device__ float g_at  [S_LEN * H_DIM];
__device__ float g_ob  [S_LEN * H_DIM];
__device__ float g_h   [S_LEN * H_DIM];
__device__ float g_xm  [S_LEN * H_DIM];
__device__ float g_lg  [S_LEN * NEXP];
__device__ int   g_tok [NEXP * S_LEN];
__device__ float g_wt  [NEXP * S_LEN];
__device__ int   g_cnt [NEXP];
__device__ float g_a1  [(size_t)NEXP * S_LEN * FF_DIM];    // gelu(xw1)*(xw3)
__device__ float g_moe [S_LEN * H_DIM];

// ---------------- fast math helpers ----------------
// tanh via exp identity with fast division; clamp avoids overflow (|x|>=15 -> +-1)
__device__ __forceinline__ float fast_tanh(float x) {
    float xc = fminf(fmaxf(x, -15.f), 15.f);
    float t = __expf(2.f * xc);
    return __fdividef(t - 1.f, t + 1.f);
}

// ---------------- small kernels ----------------
// zero ALL atomic-accumulated buffers (moe, at, ob, ls) + counts — graph-replay safe
__global__ void zero_all_kernel(float* __restrict__ moe, float* __restrict__ at,
                                float* __restrict__ ob, float* __restrict__ ls,
                                int* __restrict__ cnt) {
    int i = blockIdx.x * blockDim.x + threadIdx.x;
    if (i < S_LEN * H_DIM) { moe[i] = 0.f; at[i] = 0.f; ob[i] = 0.f; }
    if (i < NHEADS * S_LEN) ls[i] = 0.f;
    if (i < NEXP) cnt[i] = 0;
}

__global__ void rms_kernel(const float* __restrict__ in, const float* __restrict__ w,
                           const float* __restrict__ resid, float* __restrict__ out) {
    int row = blockIdx.x;
    const float* x = in + (size_t)row * H_DIM;
    __shared__ float red[256];
    float ss = 0.f;
    for (int i = threadIdx.x; i < H_DIM; i += 256) { float v = x[i]; ss += v * v; }
    red[threadIdx.x] = ss; __syncthreads();
    for (int s = 128; s > 0; s >>= 1) {
        if (threadIdx.x < s) red[threadIdx.x] += red[threadIdx.x + s];
        __syncthreads();
    }
    float inv = rsqrtf(red[0] * (1.f / H_DIM) + EPS_F);
    for (int i = threadIdx.x; i < H_DIM; i += 256) {
        float y = x[i] * inv * (1.f + w[i]);
        float r = resid ? resid[(size_t)row * H_DIM + i] : 0.f;
        out[(size_t)row * H_DIM + i] = r + y;
    }
}

// fused RoPE over Q (heads 0-7) and K (heads 8-11) of merged qkv
__global__ void rope_all_kernel(float* __restrict__ qkv, const float* __restrict__ cs,
                                const float* __restrict__ sn) {
    int idx = blockIdx.x * blockDim.x + threadIdx.x;
    int total = S_LEN * 12 * 64;
    if (idx >= total) return;
    int d = idx & 63;
    int h = (idx >> 6) % 12;
    int s = idx / (64 * 12);
    int col = (h < 8) ? h * HEADDIM : 1024 + (h - 8) * HEADDIM;
    float* row = qkv + (size_t)s * QKV_N + col;
    float x1 = row[d], x2 = row[d + 64];
    float c1 = cs[s * HEADDIM + d],      s1 = sn[s * HEADDIM + d];
    float c2 = cs[s * HEADDIM + d + 64], s2 = sn[s * HEADDIM + d + 64];
    row[d]      = x1 * c1 - x2 * s1;
    row[d + 64] = x2 * c2 + x1 * s2;
}

__global__ void transpose_v_kernel(const float* __restrict__ v, int ld,
                                   float* __restrict__ o) {
    __shared__ float t[32][33];
    int bs = blockIdx.x * 32, bd = blockIdx.y * 32;
    int tx = threadIdx.x, ty = threadIdx.y;
    #pragma unroll
    for (int j = 0; j < 32; j += 8)
        t[ty + j][tx] = v[(size_t)(bs + ty + j) * ld + bd + tx];
    __syncthreads();
    #pragma unroll
    for (int j = 0; j < 32; j += 8)
        o[(size_t)(bd + ty + j) * S_LEN + bs + tx] = t[tx][ty + j];
}

// router logits in exact f32 (parallel, one block per token, one warp per expert)
__global__ void router_kernel(const float* __restrict__ xm, const float* __restrict__ wr,
                              float* __restrict__ lg) {
    int t = blockIdx.x;
    int e = threadIdx.x >> 5, lane = threadIdx.x & 31;
    const float* x = xm + (size_t)t * H_DIM;
    const float* w = wr + (size_t)e * H_DIM;
    float s = 0.f;
    for (int i = lane * 4; i < H_DIM; i += 128) {
        float4 xv = *(const float4*)(x + i);
        float4 wv = *(const float4*)(w + i);
        s += xv.x * wv.x + xv.y * wv.y + xv.z * wv.z + xv.w * wv.w;
    }
    #pragma unroll
    for (int o = 16; o; o >>= 1) s += __shfl_xor_sync(0xffffffffu, s, o);
    if (lane == 0) lg[t * NEXP + e] = s;
}

// sparsemixer routing (parallel: one thread per token)
__global__ void route_kernel(const float* __restrict__ logits, int* __restrict__ tok,
                             float* __restrict__ wt, int* __restrict__ cnt) {
    int t = blockIdx.x * blockDim.x + threadIdx.x;
    if (t >= S_LEN) return;
    float s[NEXP];
    #pragma unroll
    for (int e = 0; e < NEXP; e++) s[e] = logits[t * NEXP + e];
    float m1 = s[0]; int sel1 = 0;
    #pragma unroll
    for (int e = 1; e < NEXP; e++) if (s[e] > m1) { m1 = s[e]; sel1 = e; }
    float v1[NEXP];
    #pragma unroll
    for (int e = 0; e < NEXP; e++) {
        float den = fmaxf(fabsf(s[e]), m1);
        v1[e] = (((m1 - s[e]) / den) > JIT2_F) ? NEG_F : s[e];
    }
    float mx1 = v1[0];
    #pragma unroll
    for (int e = 1; e < NEXP; e++) mx1 = fmaxf(mx1, v1[e]);
    float sum1 = 0.f;
    #pragma unroll
    for (int e = 0; e < NEXP; e++) sum1 += expf(v1[e] - mx1);
    float mult1 = expf(v1[sel1] - mx1) / sum1;

    float ms[NEXP];
    #pragma unroll
    for (int e = 0; e < NEXP; e++) ms[e] = (e == sel1) ? NEG_F : s[e];
    float m2 = ms[0]; int sel2 = 0;
    #pragma unroll
    for (int e = 1; e < NEXP; e++) if (ms[e] > m2) { m2 = ms[e]; sel2 = e; }
    float v2[NEXP];
    #pragma unroll
    for (int e = 0; e < NEXP; e++) {
        float den = fmaxf(fabsf(s[e]), m2);
        v2[e] = (((m2 - s[e]) / den) > JIT2_F) ? NEG_F : ms[e];
    }
    float mx2 = v2[0];
    #pragma unroll
    for (int e = 1; e < NEXP; e++) mx2 = fmaxf(mx2, v2[e]);
    float sum2 = 0.f;
    #pragma unroll
    for (int e = 0; e < NEXP; e++) sum2 += expf(v2[e] - mx2);
    float mult2 = expf(v2[sel2] - mx2) / sum2;

    int p1 = atomicAdd(&cnt[sel1], 1);
    tok[sel1 * S_LEN + p1] = t; wt[sel1 * S_LEN + p1] = mult1;
    int p2 = atomicAdd(&cnt[sel2], 1);
    tok[sel2 * S_LEN + p2] = t; wt[sel2 * S_LEN + p2] = mult2;
}

// ---------------- GEMM helpers ----------------
__device__ __forceinline__ void mma_bf16(float* c, const uint32_t* a, const uint32_t* b) {
    asm volatile(
        "mma.sync.aligned.m16n8k16.row.col.f32.bf16.bf16.f32 "
        "{%0,%1,%2,%3}, {%4,%5,%6,%7}, {%8,%9}, {%0,%1,%2,%3};\n"
        : "+f"(c[0]), "+f"(c[1]), "+f"(c[2]), "+f"(c[3])
        : "r"(a[0]), "r"(a[1]), "r"(a[2]), "r"(a[3]), "r"(b[0]), "r"(b[1]));
}

__device__ __forceinline__ void ldsm4(uint32_t& r0, uint32_t& r1, uint32_t& r2, uint32_t& r3,
                                      uint32_t saddr) {
    asm volatile("ldmatrix.sync.aligned.m8n8.x4.shared.b16 {%0,%1,%2,%3}, [%4];"
                 : "=r"(r0), "=r"(r1), "=r"(r2), "=r"(r3) : "r"(saddr));
}

// truncation split: hi = top 16 bits, lo = rn-bf16(x - hi); packs 2 values
__device__ __forceinline__ void split2t(float a, float b, uint32_t& h, uint32_t& l) {
    uint32_t ia = __float_as_uint(a), ib = __float_as_uint(b);
    h = __byte_perm(ia, ib, 0x7632);
    float la = a - __uint_as_float(ia & 0xFFFF0000u);
    float lb = b - __uint_as_float(ib & 0xFFFF0000u);
    asm("cvt.rn.bf16x2.f32 %0, %1, %2;" : "=r"(l) : "f"(lb), "f"(la));
}

__device__ __forceinline__ void cpasync16(uint32_t dst, const void* src, bool pred) {
    int sz = pred ? 16 : 0;
    asm volatile("cp.async.cg.shared.global [%0], [%1], 16, %2;\n"
                 :: "r"(dst), "l"(src), "r"(sz));
}
#define CP_COMMIT() asm volatile("cp.async.commit_group;\n" ::: "memory")
#define CP_WAIT1()  asm volatile("cp.async.wait_group 1;\n"  ::: "memory")
#define CP_WAITALL() asm volatile("cp.async.wait_all;\n"     ::: "memory")

// dynamic smem layout (bytes):
//   f32 A stages: 0      + s*8192   (3 stages, 24KB)
//   f32 B stages: 24576  + s*8192   (3 stages, 24KB)
//   bf16 bufs (b=0,1) at 49152 + b*24576: Ah +0, Al +6144, Bh +12288, Bl +18432
#define GSMEM 98304

// EPI: 0 plain/atomic/scatter, 1 = exp(softcap)+causal zero + atomic row-sums,
//      2 = gelu(w1)*w3 pair (with SEG==3)
// CAUSAL: 0 none, 1 scores (skip masked blocks), 2 PV (k limited to m0+128)
// SEG: 0 none, 1 = 3-way B select (QKV), 3 = w1/w3 interleaved-16 (fused MoE up)
// RS: scale output by 1/roww[z*S_LEN + m]
template<int EPI, bool GATHER, bool SCATTER, bool ATOMIC, int CAUSAL, int SEG, bool RS>
__global__ void __launch_bounds__(256, 2)
gemm3f_kernel(const float* __restrict__ A, int lda, long long sAz,
              const float* __restrict__ B, const float* __restrict__ B2,
              const float* __restrict__ B3,
              int ldb, long long sBz, int bdiv,
              float* __restrict__ C, float* __restrict__ C2, int ldc, long long sCz,
              int M, int N, int K, int KS, int seg1, int seg2,
              const int* __restrict__ rowidx, const float* __restrict__ roww,
              const int* __restrict__ counts, float* __restrict__ lsout) {
    extern __shared__ char dsm[];
    int zz = blockIdx.z;
    int z  = zz / KS, kc = zz - z * KS;
    int m0 = blockIdx.y * 128;
    int n0 = blockIdx.x * 128;

    if (CAUSAL == 1 && n0 >= m0 + 128) return;

    int Mact = M;
    const int*   ridx = nullptr;
    const float* rw   = nullptr;
    if (counts) {
        Mact = counts[z];
        ridx = rowidx + z * S_LEN;
        rw   = roww ? (roww + z * S_LEN) : nullptr;
        if (m0 >= Mact) return;
    }

    const float* Bsel = B;
    int nbase = 0;
    if constexpr (SEG == 1) {
        if (n0 >= seg2)      { Bsel = B3; nbase = seg2; }
        else if (n0 >= seg1) { Bsel = B2; nbase = seg1; }
    }

    int keff = (CAUSAL == 2) ? min(K, m0 + 128) : K;
    int chunk = K / KS;
    int kstart = kc * chunk;
    int kend   = min(kstart + chunk, keff);
    if (kstart >= kend) return;

    const float* Az = A + (long long)z * sAz;
    const float* Bz = Bsel + (long long)(z / bdiv) * sBz;

    int tid  = threadIdx.x;
    int lane = tid & 31;
    int warp = tid >> 5;
    int wm = warp >> 2, wn = warp & 3;
    int g  = lane >> 2, tg = lane & 3;

    uint32_t sbase = (uint32_t)__cvta_generic_to_shared(dsm);

    // cp.async staging coordinates (2 chunks of 16B per tile per thread)
    const float* srcA[2]; const float* srcB[2];
    uint32_t dstO[2];
    bool pA[2], pB[2];
    #pragma unroll
    for (int j = 0; j < 2; ++j) {
        int id  = tid + 256 * j;
        int row = id >> 2, c4 = (id & 3) * 4;
        int csw = c4 ^ (4 * (row & 3));
        dstO[j] = (uint32_t)((row * 16 + csw) * 4);
        pA[j] = (m0 + row) < Mact;
        long long ar = 0;
        if (pA[j]) ar = GATHER ? (long long)ridx[m0 + row] : (long long)(m0 + row);
        srcA[j] = Az + ar * (long long)lda + c4;
        if constexpr (SEG == 3) {
            int w   = row >> 5, sub = row & 31;
            int col = (n0 >> 1) + w * 16 + (sub & 15);
            const float* basep = (sub & 16) ? B2 : B;
            srcB[j] = basep + (long long)z * sBz + (long long)col * ldb + c4;
            pB[j] = true;
        } else {
            pB[j] = (n0 + row) < N;
            srcB[j] = Bz + (pB[j] ? (long long)(n0 + row - nbase) : 0ll) * (long long)ldb + c4;
        }
    }

    // ldmatrix lane offsets (bytes), SM_STRIDE = 12 u32 rows
    uint32_t a_lane = (uint32_t)(((lane & 15) * 12 + (lane >> 4) * 4) * 4);
    uint32_t b_lane = (uint32_t)((((lane & 7) + ((lane >> 4) & 1) * 8) * 12
                                  + ((lane >> 3) & 1) * 4) * 4);
    uint32_t awoff = (uint32_t)(wm * 64 * 12 * 4) + a_lane;
    uint32_t bwoff = (uint32_t)(wn * 32 * 12 * 4) + b_lane;

    // convert-phase coordinates
    int crow = tid >> 1, ch = tid & 1;
    int cxm  = 4 * (crow & 3);
    int co0  = crow * 16 + ((8 * ch) ^ cxm);
    int co1  = crow * 16 + ((8 * ch + 4) ^ cxm);
    int cdst = crow * 3 + ch;   // uint4 index: (row*12 + h*4) u32 / 4

    float acc[4][4][4];
    #pragma unroll
    for (int i = 0; i < 4; i++)
        #pragma unroll
        for (int j = 0; j < 4; j++)
            #pragma unroll
            for (int r = 0; r < 4; r++) acc[i][j][r] = 0.f;

    int nk = (kend - kstart) >> 4;

    // prologue: prefetch f32 stages 0,1
    #pragma unroll
    for (int pf = 0; pf < 2; ++pf) {
        if (pf < nk) {
            int k0 = kstart + pf * 16;
            uint32_t aoff = sbase + (uint32_t)(pf * 8192);
            uint32_t boff = sbase + 24576u + (uint32_t)(pf * 8192);
            #pragma unroll
            for (int j = 0; j < 2; ++j) {
                cpasync16(aoff + dstO[j], srcA[j] + k0, pA[j]);
                cpasync16(boff + dstO[j], srcB[j] + k0, pB[j]);
            }
        }
        CP_COMMIT();
    }

    for (int it = 0; it < nk; ++it) {
        CP_WAIT1();
        __syncthreads();   // f32 stage it%3 ready; bf16 buf it&1 free

        int pf = it + 2;
        if (pf < nk) {
            int st = pf % 3;
            int k0 = kstart + pf * 16;
            uint32_t aoff = sbase + (uint32_t)(st * 8192);
            uint32_t boff = sbase + 24576u + (uint32_t)(st * 8192);
            #pragma unroll
            for (int j = 0; j < 2; ++j) {
                cpasync16(aoff + dstO[j], srcA[j] + k0, pA[j]);
                cpasync16(boff + dstO[j], srcB[j] + k0, pB[j]);
            }
        }
        CP_COMMIT();

        int cs = it % 3, cb = it & 1;
        // ---- convert f32 stage -> hi/lo bf16 tiles (split once per element)
        {
            const float* fA = (const float*)(dsm + (size_t)cs * 8192);
            const float* fB = (const float*)(dsm + 24576 + (size_t)cs * 8192);
            uint4* Ah = (uint4*)(dsm + 49152 + (size_t)cb * 24576);
            uint4* Al = (uint4*)(dsm + 49152 + (size_t)cb * 24576 + 6144);
            uint4* Bh = (uint4*)(dsm + 49152 + (size_t)cb * 24576 + 12288);
            uint4* Bl = (uint4*)(dsm + 49152 + (size_t)cb * 24576 + 18432);
            float4 a0 = *(const float4*)(fA + co0);
            float4 a1 = *(const float4*)(fA + co1);
            uint4 hh, ll;
            split2t(a0.x, a0.y, hh.x, ll.x); split2t(a0.z, a0.w, hh.y, ll.y);
            split2t(a1.x, a1.y, hh.z, ll.z); split2t(a1.z, a1.w, hh.w, ll.w);
            Ah[cdst] = hh; Al[cdst] = ll;
            float4 b0 = *(const float4*)(fB + co0);
            float4 b1 = *(const float4*)(fB + co1);
            split2t(b0.x, b0.y, hh.x, ll.x); split2t(b0.z, b0.w, hh.y, ll.y);
            split2t(b1.x, b1.y, hh.z, ll.z); split2t(b1.z, b1.w, hh.w, ll.w);
            Bh[cdst] = hh; Bl[cdst] = ll;
        }
        __syncthreads();   // bf16 tiles ready

        // ---- fragment loads (ldmatrix) + pass-ordered MMAs
        uint32_t bb     = sbase + 49152u + (uint32_t)(cb * 24576);
        uint32_t abase  = bb + awoff;
        uint32_t albase = bb + 6144u + awoff;
        uint32_t bbase  = bb + 12288u + bwoff;
        uint32_t blbase = bb + 18432u + bwoff;

        uint32_t bh[4][2], bl[4][2];
        ldsm4(bh[0][0], bh[0][1], bh[1][0], bh[1][1], bbase);
        ldsm4(bh[2][0], bh[2][1], bh[3][0], bh[3][1], bbase + 768);
        ldsm4(bl[0][0], bl[0][1], bl[1][0], bl[1][1], blbase);
        ldsm4(bl[2][0], bl[2][1], bl[3][0], bl[3][1], blbase + 768);

        #pragma unroll
        for (int mt = 0; mt < 4; ++mt) {
            uint32_t ah[4], al[4];
            ldsm4(ah[0], ah[1], ah[2], ah[3], abase + mt * 768);
            ldsm4(al[0], al[1], al[2], al[3], albase + mt * 768);
            #pragma unroll
            for (int nt = 0; nt < 4; ++nt) mma_bf16(acc[mt][nt], ah, bh[nt]);
            #pragma unroll
            for (int nt = 0; nt < 4; ++nt) mma_bf16(acc[mt][nt], ah, bl[nt]);
            #pragma unroll
            for (int nt = 0; nt < 4; ++nt) mma_bf16(acc[mt][nt], al, bh[nt]);
        }
    }
    CP_WAITALL();

    // ---- epilogue
    float* Cz = C + (long long)z * sCz;
    if constexpr (EPI == 2) {
        // fused gelu(xw1)*(xw3) with fast tanh (fast division)
        #pragma unroll
        for (int mt = 0; mt < 4; ++mt) {
            int row0 = m0 + wm * 64 + mt * 16 + g;
            #pragma unroll
            for (int nt = 0; nt < 2; ++nt) {
                int col0 = (n0 >> 1) + wn * 16 + nt * 8 + 2 * tg;
                #pragma unroll
                for (int r = 0; r < 4; ++r) {
                    int m = row0 + (r >> 1) * 8;
                    if (m >= Mact) continue;
                    int col = col0 + (r & 1);
                    float v1 = acc[mt][nt][r];
                    float v3 = acc[mt][nt + 2][r];
                    float gg = 0.5f * v1 * (1.f + fast_tanh(0.7978845608028654f *
                               (v1 + 0.044715f * v1 * v1 * v1)));
                    Cz[(long long)m * ldc + col] = gg * v3;
                }
            }
        }
        return;
    }
    const float* rsc = nullptr;
    if constexpr (RS) rsc = roww + (long long)z * S_LEN;
    float rs[4][2];
    if constexpr (EPI == 1) {
        #pragma unroll
        for (int i = 0; i < 4; i++) { rs[i][0] = 0.f; rs[i][1] = 0.f; }
    }
    #pragma unroll
    for (int mt = 0; mt < 4; ++mt) {
        int row0 = m0 + wm * 64 + mt * 16 + g;
        #pragma unroll
        for (int nt = 0; nt < 4; ++nt) {
            int col0 = n0 + wn * 32 + nt * 8 + 2 * tg;
            #pragma unroll
            for (int r = 0; r < 4; ++r) {
                int m = row0 + (r >> 1) * 8;
                int n = col0 + (r & 1);
                if (m >= Mact || n >= N) continue;
                float v = acc[mt][nt][r];
                if constexpr (EPI == 1) {
                    float e = 0.f;
                    if (n <= m)
                        e = __expf(SOFTCAP_F * fast_tanh(v * (SCALING_F / SOFTCAP_F)));
                    Cz[(long long)m * ldc + n] = e;
                    rs[mt][r >> 1] += e;
                } else {
                    if constexpr (RS) v = v / rsc[m];
                    if constexpr (SCATTER) {
                        atomicAdd(&Cz[(long long)ridx[m] * ldc + n], rw[m] * v);
                    } else if constexpr (ATOMIC) {
                        atomicAdd(&Cz[(long long)m * ldc + n], v);
                    } else {
                        Cz[(long long)m * ldc + n] = v;
                    }
                }
            }
        }
    }
    if constexpr (EPI == 1) {
        float* lsz = lsout + (long long)z * S_LEN;
        #pragma unroll
        for (int mt = 0; mt < 4; ++mt)
            #pragma unroll
            for (int rh = 0; rh < 2; ++rh) {
                float s = rs[mt][rh];
                s += __shfl_xor_sync(0xffffffffu, s, 1);
                s += __shfl_xor_sync(0xffffffffu, s, 2);
                if (tg == 0) {
                    int m = m0 + wm * 64 + mt * 16 + g + 8 * rh;
                    atomicAdd(&lsz[m], s);
                }
            }
    }
}

// ---------------- launcher ----------------
#define KSPV 8

extern "C" void kernel_launch(void* const* d_in, const int* in_sizes, int n_in,
                              void* d_out, int out_size) {
    const float* hidden = (const float*)d_in[0];
    const float* cosb   = (const float*)d_in[1];
    const float* sinb   = (const float*)d_in[2];
    const float* wq     = (const float*)d_in[4];
    const float* wk     = (const float*)d_in[5];
    const float* wv     = (const float*)d_in[6];
    const float* wo     = (const float*)d_in[7];
    const float* wr     = (const float*)d_in[8];
    const float* w1     = (const float*)d_in[9];
    const float* w2     = (const float*)d_in[10];
    const float* w3     = (const float*)d_in[11];
    const float* ln_in  = (const float*)d_in[12];
    const float* ln_pa  = (const float*)d_in[13];
    const float* ln_pf  = (const float*)d_in[14];
    const float* ln_po  = (const float*)d_in[15];
    float* out = (float*)d_out;

    float *xb,*qkvb,*vtb,*scb,*lsb,*atb,*obb,*hb,*xmb,*lgb,*wtb,*a1b,*moeb;
    int *tokb,*cntb;
    cudaGetSymbolAddress((void**)&xb, g_x);    cudaGetSymbolAddress((void**)&qkvb,g_qkv);
    cudaGetSymbolAddress((void**)&vtb,g_vt);   cudaGetSymbolAddress((void**)&scb,g_sc);
    cudaGetSymbolAddress((void**)&lsb,g_ls);
    cudaGetSymbolAddress((void**)&atb,g_at);   cudaGetSymbolAddress((void**)&obb,g_ob);
    cudaGetSymbolAddress((void**)&hb, g_h);    cudaGetSymbolAddress((void**)&xmb,g_xm);
    cudaGetSymbolAddress((void**)&lgb,g_lg);   cudaGetSymbolAddress((void**)&wtb,g_wt);
    cudaGetSymbolAddress((void**)&a1b,g_a1);
    cudaGetSymbolAddress((void**)&moeb,g_moe);
    cudaGetSymbolAddress((void**)&tokb,g_tok); cudaGetSymbolAddress((void**)&cntb,g_cnt);

    // dynamic-smem opt-in for every GEMM instantiation (host-side, idempotent)
    cudaFuncSetAttribute(gemm3f_kernel<0,false,false,false,0,1,false>,
                         cudaFuncAttributeMaxDynamicSharedMemorySize, GSMEM);
    cudaFuncSetAttribute(gemm3f_kernel<1,false,false,false,1,0,false>,
                         cudaFuncAttributeMaxDynamicSharedMemorySize, GSMEM);
    cudaFuncSetAttribute(gemm3f_kernel<0,false,false,true,2,0,true>,
                         cudaFuncAttributeMaxDynamicSharedMemorySize, GSMEM);
    cudaFuncSetAttribute(gemm3f_kernel<0,false,false,true,0,0,false>,
                         cudaFuncAttributeMaxDynamicSharedMemorySize, GSMEM);
    cudaFuncSetAttribute(gemm3f_kernel<2,true,false,false,0,3,false>,
                         cudaFuncAttributeMaxDynamicSharedMemorySize, GSMEM);
    cudaFuncSetAttribute(gemm3f_kernel<0,false,true,false,0,0,false>,
                         cudaFuncAttributeMaxDynamicSharedMemorySize, GSMEM);

    zero_all_kernel<<<(S_LEN * H_DIM + 255) / 256, 256>>>(moeb, atb, obb, lsb, cntb);
    rms_kernel<<<S_LEN, 256>>>(hidden, ln_in, nullptr, xb);

    // merged QKV projection: N = 1024(Q) + 512(K) + 512(V)
    gemm3f_kernel<0,false,false,false,0,1,false><<<dim3(16,16,1),256,GSMEM>>>(
        xb, H_DIM, 0, wq, wk, wv, H_DIM, 0, 1,
        qkvb, nullptr, QKV_N, 0,
        S_LEN, QKV_N, H_DIM, 1, 1024, 1536, nullptr, nullptr, nullptr, nullptr);

    // fused RoPE over Q and K heads (measured win in R15)
    rope_all_kernel<<<(S_LEN*12*64+255)/256, 256>>>(qkvb, cosb, sinb);
    transpose_v_kernel<<<dim3(S_LEN/32, KVHEADS*HEADDIM/32), dim3(32,8)>>>(qkvb + 1536, QKV_N, vtb);

    // attention scores -> exp(softcap) + row sums (fused softmax, fast math)
    gemm3f_kernel<1,false,false,false,1,0,false><<<dim3(16,16,NHEADS),256,GSMEM>>>(
        qkvb, QKV_N, HEADDIM, qkvb + 1024, nullptr, nullptr, QKV_N, HEADDIM, 2,
        scb, nullptr, S_LEN, (long long)S_LEN*S_LEN,
        S_LEN, S_LEN, HEADDIM, 1, 0, 0, nullptr, nullptr, nullptr, lsb);

    // P @ V^T: causal k-limit + split-K=8 atomic; normalize by 1/ls[m]
    gemm3f_kernel<0,false,false,true,2,0,true><<<dim3(1,16,NHEADS*KSPV),256,GSMEM>>>(
        scb, S_LEN, (long long)S_LEN*S_LEN, vtb, nullptr, nullptr, S_LEN,
        (long long)HEADDIM*S_LEN, 2,
        atb, nullptr, H_DIM, HEADDIM,
        S_LEN, HEADDIM, S_LEN, KSPV, 0, 0, nullptr, lsb, nullptr, nullptr);

    // O projection (split-K=2, atomic into zeroed g_ob)
    gemm3f_kernel<0,false,false,true,0,0,false><<<dim3(8,16,2),256,GSMEM>>>(
        atb, H_DIM, 0, wo, nullptr, nullptr, H_DIM, 0, 1,
        obb, nullptr, H_DIM, 0,
        S_LEN, H_DIM, H_DIM, 2, 0, 0, nullptr, nullptr, nullptr, nullptr);

    rms_kernel<<<S_LEN, 256>>>(obb, ln_pa, hidden, hb);
    rms_kernel<<<S_LEN, 256>>>(hb, ln_pf, nullptr, xmb);

    // parallel router + sparsemixer routing (reverted from fused version)
    router_kernel<<<S_LEN, 256>>>(xmb, wr, lgb);
    route_kernel<<<(S_LEN+255)/256, 256>>>(lgb, tokb, wtb, cntb);

    // fused MoE up: w1/w3 interleaved-16, gelu(xw1)*(xw3) epilogue -> a1 only
    gemm3f_kernel<2,true,false,false,0,3,false><<<dim3(32,16,NEXP),256,GSMEM>>>(
        xmb, H_DIM, 0, w1, w3, nullptr, H_DIM, (long long)FF_DIM*H_DIM, 1,
        a1b, nullptr, FF_DIM, (long long)S_LEN*FF_DIM,
        S_LEN, 2*FF_DIM, H_DIM, 1, 0, 0, tokb, nullptr, cntb, nullptr);

    // MoE down-projection: split-K=2 + weighted scatter-add
    gemm3f_kernel<0,false,true,false,0,0,false><<<dim3(8,16,NEXP*2),256,GSMEM>>>(
        a1b, FF_DIM, (long long)S_LEN*FF_DIM, w2, nullptr, nullptr, FF_DIM,
        (long long)H_DIM*FF_DIM, 1,
        moeb, nullptr, H_DIM, 0,
        S_LEN, H_DIM, FF_DIM, 2, 0, 0, tokb, wtb, cntb, nullptr);

    rms_kernel<<<S_LEN, 256>>>(moeb, ln_po, hb, out);
}